// round 9
// baseline (speedup 1.0000x reference)
#include <cuda_runtime.h>

// EKF cell: B=262144, N=8, M=4. Persistent single-warp CTAs, one thread/batch,
// 32 batches per tile, ~14 tiles per CTA, cross-tile DOUBLE-BUFFERED TMA:
// while computing tile i, tile i+2's full input set (F/P/H/pn/mn, 26.4KB)
// streams into the other stage. Cov output staged in the dead F region and
// bulk-stored. XOR bank-permutation for conflict-free smem<->reg transposes.
//
// Stage layout (float4 units, per stage of 1648):
//   F [0,512)  P [512,1024)  H [1024,1280)  pn [1280,1568)  mn [1568,1648)
// mbar[2] at f4 3296. Dynamic smem 52768B -> 4 CTAs/SM.

#define STAGE_F4 1648
#define MBAR_F4  3296
#define SMEM_BYTES (MBAR_F4 * 16 + 32)
#define TXALL 26368u     // 8192+8192+4096+4608+1280
#define MAX_GRID 608

__device__ __forceinline__ float psym(const float* t, int i, int j) {
    return (i >= j) ? t[i*(i+1)/2 + j] : t[j*(j+1)/2 + i];
}
__device__ __forceinline__ unsigned sptr(const void* p) {
    return (unsigned)__cvta_generic_to_shared(p);
}
__device__ __forceinline__ void bulk_g2s(unsigned dst, const void* src,
                                         unsigned bytes, unsigned mbar) {
    asm volatile(
        "cp.async.bulk.shared::cluster.global.mbarrier::complete_tx::bytes [%0], [%1], %2, [%3];"
        :: "r"(dst), "l"(src), "r"(bytes), "r"(mbar) : "memory");
}
__device__ __forceinline__ void bulk_s2g(void* dst, unsigned src, unsigned bytes) {
    asm volatile(
        "cp.async.bulk.global.shared::cta.bulk_group [%0], [%1], %2;"
        :: "l"(dst), "r"(src), "r"(bytes) : "memory");
}
__device__ __forceinline__ void mbar_wait(unsigned mbar, int parity) {
    asm volatile(
        "{\n\t"
        ".reg .pred P;\n"
        "W%=:\n\t"
        "mbarrier.try_wait.parity.shared.b64 P, [%0], %1;\n\t"
        "@!P bra W%=;\n\t"
        "}"
        :: "r"(mbar), "r"(parity) : "memory");
}

__global__ __launch_bounds__(32, 4) void ekf_kernel(
    const float* __restrict__ g_meas,
    const float* __restrict__ g_state,
    const float* __restrict__ g_cov,
    const float* __restrict__ g_F,
    const float* __restrict__ g_H,
    const float* __restrict__ g_pn,
    const float* __restrict__ g_mn,
    float* __restrict__ o_pred,
    float* __restrict__ o_state,
    float* __restrict__ o_cov,
    int B)
{
    extern __shared__ __align__(16) float4 s4m[];

    const int lane = threadIdx.x;
    const int lx = lane & 7;
    const int tiles = (B + 31) >> 5;
    const int GR = gridDim.x;
    const unsigned smb   = sptr(s4m);
    const unsigned mbar0 = smb + MBAR_F4 * 16;

    if (lane == 0) {
        asm volatile("mbarrier.init.shared.b64 [%0], 1;" :: "r"(mbar0) : "memory");
        asm volatile("mbarrier.init.shared.b64 [%0], 1;" :: "r"(mbar0 + 8) : "memory");
        asm volatile("fence.proxy.async.shared::cta;" ::: "memory");
    }
    __syncwarp();

    // ---------- prologue: prefetch tiles for iterations 0 and 1 ----------
    if (lane == 0) {
        #pragma unroll
        for (int k = 0; k < 2; k++) {
            int t = blockIdx.x + k * GR;
            if (t < tiles) {
                int wb = t * 32; if (wb + 32 > B) wb = B - 32;
                unsigned stg = smb + k * STAGE_F4 * 16;
                unsigned mb  = mbar0 + k * 8;
                asm volatile("mbarrier.arrive.expect_tx.shared.b64 _, [%0], %1;"
                             :: "r"(mb), "r"(TXALL) : "memory");
                bulk_g2s(stg,             g_F   + (size_t)wb * 64, 8192, mb);
                bulk_g2s(stg + 512 * 16,  g_cov + (size_t)wb * 64, 8192, mb);
                bulk_g2s(stg + 1024 * 16, g_H   + (size_t)wb * 32, 4096, mb);
                bulk_g2s(stg + 1280 * 16, g_pn  + (size_t)wb * 36, 4608, mb);
                bulk_g2s(stg + 1568 * 16, g_mn  + (size_t)wb * 10, 1280, mb);
            }
        }
    }

    int it = 0;
    for (int tile = blockIdx.x; tile < tiles; tile += GR, it++) {
        const int buf = it & 1;
        float4* sb = s4m + buf * STAGE_F4;
        const unsigned mb = mbar0 + buf * 8;
        int wb = tile * 32; if (wb + 32 > B) wb = B - 32;
        const int b = wb + lane;

        // issue per-lane coalesced loads before the wait (overlap)
        float st[8]; float4 mv;
        {
            mv = reinterpret_cast<const float4*>(g_meas)[b];
            const float4* s4 = reinterpret_cast<const float4*>(g_state) + (size_t)b * 2;
            float4 a = s4[0], c = s4[1];
            st[0]=a.x; st[1]=a.y; st[2]=a.z; st[3]=a.w;
            st[4]=c.x; st[5]=c.y; st[6]=c.z; st[7]=c.w;
        }

        mbar_wait(mb, (it >> 1) & 1);
        __syncwarp();

        // ---- in-place XOR perm of F and P (lane-private read-back) ----
        #pragma unroll
        for (int base = 512; base >= 0; base -= 512) {      // P then F
            float4 t[8];
            #pragma unroll
            for (int k = 0; k < 8; k++) t[k] = sb[base + lane + 32*k];
            __syncwarp();
            #pragma unroll
            for (int k = 0; k < 8; k++) {
                int g = lane + 32*k;
                int bt = g >> 4, sl = g & 15;
                sb[base + bt*16 + (sl ^ (bt & 7))] = t[k];
            }
            __syncwarp();
            #pragma unroll
            for (int k = 0; k < 8; k++) t[k] = sb[base + 256 + lane + 32*k];
            __syncwarp();
            #pragma unroll
            for (int k = 0; k < 8; k++) {
                int g = 256 + lane + 32*k;
                int bt = g >> 4, sl = g & 15;
                sb[base + bt*16 + (sl ^ (bt & 7))] = t[k];
            }
            __syncwarp();
        }

        // ---- unpack F (64) and P (tri 36), conflict-free ----
        float Fm[64];
        #pragma unroll
        for (int v = 0; v < 16; v++) {
            float4 x = sb[lane*16 + ((v & 8) | ((v ^ lx) & 7))];
            Fm[4*v+0] = x.x; Fm[4*v+1] = x.y; Fm[4*v+2] = x.z; Fm[4*v+3] = x.w;
        }
        float Pt[36];
        #pragma unroll
        for (int v = 0; v < 16; v++) {
            float4 x = sb[512 + lane*16 + ((v & 8) | ((v ^ lx) & 7))];
            float vals[4] = {x.x, x.y, x.z, x.w};
            #pragma unroll
            for (int c = 0; c < 4; c++) {
                int e = 4*v + c, i = e >> 3, j = e & 7;
                if (i >= j) Pt[i*(i+1)/2 + j] = vals[c];
            }
        }

        // ---- in-place XOR perm of H ----
        __syncwarp();
        {
            float4 t[4];
            #pragma unroll
            for (int k = 0; k < 4; k++) t[k] = sb[1024 + lane + 32*k];
            __syncwarp();
            #pragma unroll
            for (int k = 0; k < 4; k++) {
                int g = lane + 32*k;
                int bt = g >> 3, sl = g & 7;
                sb[1024 + bt*8 + (sl ^ (bt & 7))] = t[k];
            }
            __syncwarp();
            #pragma unroll
            for (int k = 0; k < 4; k++) t[k] = sb[1024 + 128 + lane + 32*k];
            __syncwarp();
            #pragma unroll
            for (int k = 0; k < 4; k++) {
                int g = 128 + lane + 32*k;
                int bt = g >> 3, sl = g & 7;
                sb[1024 + bt*8 + (sl ^ (bt & 7))] = t[k];
            }
            __syncwarp();
        }

        // ---- new_state = F @ state ----
        float ns[8];
        #pragma unroll
        for (int i = 0; i < 8; i++) {
            float a = 0.f;
            #pragma unroll
            for (int j = 0; j < 8; j++) a += Fm[i*8+j] * st[j];
            ns[i] = a;
        }
        // ---- P' = F P F^T (column-strip, lower tri) ----
        float Pp[36];
        #pragma unroll
        for (int l = 0; l < 8; l++) {
            float g[8];
            #pragma unroll
            for (int j = 0; j < 8; j++) {
                float a = 0.f;
                #pragma unroll
                for (int k = 0; k < 8; k++) a += psym(Pt, j, k) * Fm[l*8+k];
                g[j] = a;
            }
            #pragma unroll
            for (int i = l; i < 8; i++) {
                float a = 0.f;
                #pragma unroll
                for (int j = 0; j < 8; j++) a += Fm[i*8+j] * g[j];
                Pp[i*(i+1)/2 + l] = a;
            }
        }

        // ---- P' += Q = Lq Lq^T ----
        {
            float Lq[36];
            #pragma unroll
            for (int v = 0; v < 9; v++) {
                float4 x = sb[1280 + lane*9 + v];
                Lq[4*v+0] = x.x; Lq[4*v+1] = x.y; Lq[4*v+2] = x.z; Lq[4*v+3] = x.w;
            }
            #pragma unroll
            for (int i = 0; i < 8; i++) {
                #pragma unroll
                for (int l = 0; l <= i; l++) {
                    float a = Pp[i*(i+1)/2 + l];
                    #pragma unroll
                    for (int k = 0; k <= l; k++)
                        a += Lq[i*(i+1)/2 + k] * Lq[l*(l+1)/2 + k];
                    Pp[i*(i+1)/2 + l] = a;
                }
            }
        }

        // ---- H; prediction (stored immediately); residual ----
        float Hm[32];
        #pragma unroll
        for (int v = 0; v < 8; v++) {
            float4 x = sb[1024 + lane*8 + (v ^ lx)];
            Hm[4*v+0] = x.x; Hm[4*v+1] = x.y; Hm[4*v+2] = x.z; Hm[4*v+3] = x.w;
        }
        float res[4];
        {
            float pr[4];
            #pragma unroll
            for (int i = 0; i < 4; i++) {
                float a = 0.f;
                #pragma unroll
                for (int j = 0; j < 8; j++) a += Hm[i*8+j] * ns[j];
                pr[i] = a;
            }
            reinterpret_cast<float4*>(o_pred)[b] = make_float4(pr[0], pr[1], pr[2], pr[3]);
            res[0] = mv.x - pr[0]; res[1] = mv.y - pr[1];
            res[2] = mv.z - pr[2]; res[3] = mv.w - pr[3];
        }

        // ---- PHt = P' @ H^T ----
        float PHt[32];
        #pragma unroll
        for (int i = 0; i < 8; i++) {
            #pragma unroll
            for (int j = 0; j < 4; j++) {
                float a = 0.f;
                #pragma unroll
                for (int k = 0; k < 8; k++) a += psym(Pp, i, k) * Hm[j*8+k];
                PHt[i*4+j] = a;
            }
        }

        // ---- S = H @ PHt + R ----
        float A[16];
        {
            float Lr[10];
            const float2* s2 = reinterpret_cast<const float2*>(sb + 1568);
            #pragma unroll
            for (int v = 0; v < 5; v++) {
                float2 x = s2[lane*5 + v];
                Lr[2*v] = x.x; Lr[2*v+1] = x.y;
            }
            #pragma unroll
            for (int i = 0; i < 4; i++) {
                #pragma unroll
                for (int j = 0; j < 4; j++) {
                    float a = 0.f;
                    #pragma unroll
                    for (int k = 0; k <= ((i < j) ? i : j); k++)
                        a += Lr[i*(i+1)/2 + k] * Lr[j*(j+1)/2 + k];
                    #pragma unroll
                    for (int k = 0; k < 8; k++) a += Hm[i*8+k] * PHt[k*4+j];
                    A[i*4+j] = a;
                }
            }
        }

        // ---- Gauss-Jordan solve S X = [PHt^T | res] ----
        float Rh[36];
        #pragma unroll
        for (int r = 0; r < 4; r++) {
            #pragma unroll
            for (int c = 0; c < 8; c++) Rh[r*9+c] = PHt[c*4+r];
            Rh[r*9+8] = res[r];
        }
        #pragma unroll
        for (int c = 0; c < 4; c++) {
            float inv = 1.0f / A[c*4+c];
            #pragma unroll
            for (int j = 0; j < 4; j++) A[c*4+j] *= inv;
            #pragma unroll
            for (int j = 0; j < 9; j++) Rh[c*9+j] *= inv;
            #pragma unroll
            for (int r = 0; r < 4; r++) {
                if (r == c) continue;
                float f = A[r*4+c];
                #pragma unroll
                for (int j = 0; j < 4; j++) A[r*4+j] -= f * A[c*4+j];
                #pragma unroll
                for (int j = 0; j < 9; j++) Rh[r*9+j] -= f * Rh[c*9+j];
            }
        }

        // ---- upd_state; store ----
        {
            float us[8];
            #pragma unroll
            for (int i = 0; i < 8; i++) {
                float a = ns[i];
                #pragma unroll
                for (int j = 0; j < 4; j++) a += PHt[i*4+j] * Rh[j*9+8];
                us[i] = a;
            }
            float4* s4o = reinterpret_cast<float4*>(o_state) + (size_t)b * 2;
            s4o[0] = make_float4(us[0], us[1], us[2], us[3]);
            s4o[1] = make_float4(us[4], us[5], us[6], us[7]);
        }

        // ---- upd_cov: stage perm'd in dead F region, compress, bulk store ----
        float UC[36];
        #pragma unroll
        for (int i = 0; i < 8; i++) {
            #pragma unroll
            for (int l = 0; l <= i; l++) {
                float a = Pp[i*(i+1)/2 + l];
                #pragma unroll
                for (int j = 0; j < 4; j++) a -= PHt[i*4+j] * Rh[j*9+l];
                UC[i*(i+1)/2 + l] = a;
            }
        }
        #pragma unroll
        for (int v = 0; v < 16; v++) {
            int e = 4*v;
            sb[lane*16 + ((v & 8) | ((v ^ lx) & 7))] = make_float4(
                psym(UC, (e+0) >> 3, (e+0) & 7),
                psym(UC, (e+1) >> 3, (e+1) & 7),
                psym(UC, (e+2) >> 3, (e+2) & 7),
                psym(UC, (e+3) >> 3, (e+3) & 7));
        }
        __syncwarp();
        #pragma unroll
        for (int c = 0; c < 4; c++) {
            float4 t[4];
            #pragma unroll
            for (int k = 0; k < 4; k++) {
                int g = lane + 32*(4*c + k);
                int bt = g >> 4, sl = g & 15;
                t[k] = sb[bt*16 + ((sl & 8) | ((sl ^ bt) & 7))];
            }
            __syncwarp();
            #pragma unroll
            for (int k = 0; k < 4; k++) sb[lane + 32*(4*c + k)] = t[k];
            __syncwarp();
        }
        asm volatile("fence.proxy.async.shared::cta;" ::: "memory");
        if (lane == 0) {
            bulk_s2g(o_cov + (size_t)wb * 64, sptr(sb), 8192);
            asm volatile("cp.async.bulk.commit_group;" ::: "memory");
            asm volatile("cp.async.bulk.wait_group 0;" ::: "memory");  // smem reads done
            // re-arm this buffer: prefetch tile for iteration it+2
            int nt = tile + 2 * GR;
            if (nt < tiles) {
                int nwb = nt * 32; if (nwb + 32 > B) nwb = B - 32;
                unsigned stg = smb + buf * STAGE_F4 * 16;
                asm volatile("mbarrier.arrive.expect_tx.shared.b64 _, [%0], %1;"
                             :: "r"(mb), "r"(TXALL) : "memory");
                bulk_g2s(stg,             g_F   + (size_t)nwb * 64, 8192, mb);
                bulk_g2s(stg + 512 * 16,  g_cov + (size_t)nwb * 64, 8192, mb);
                bulk_g2s(stg + 1024 * 16, g_H   + (size_t)nwb * 32, 4096, mb);
                bulk_g2s(stg + 1280 * 16, g_pn  + (size_t)nwb * 36, 4608, mb);
                bulk_g2s(stg + 1568 * 16, g_mn  + (size_t)nwb * 10, 1280, mb);
            }
        }
        __syncwarp();
    }
}

extern "C" void kernel_launch(void* const* d_in, const int* in_sizes, int n_in,
                              void* d_out, int out_size)
{
    const float* g_meas = (const float*)d_in[0];
    const float* g_state = (const float*)d_in[1];
    const float* g_cov  = (const float*)d_in[2];
    const float* g_F    = (const float*)d_in[3];
    const float* g_H    = (const float*)d_in[4];
    const float* g_pn   = (const float*)d_in[5];
    const float* g_mn   = (const float*)d_in[6];

    int B = in_sizes[0] / 4;   // measurement is (B, 4)

    float* o_pred  = (float*)d_out;
    float* o_state = o_pred + (size_t)B * 4;
    float* o_cov   = o_state + (size_t)B * 8;

    cudaFuncSetAttribute(ekf_kernel, cudaFuncAttributeMaxDynamicSharedMemorySize,
                         SMEM_BYTES);

    int tiles = (B + 31) / 32;
    int grid = tiles < MAX_GRID ? tiles : MAX_GRID;
    ekf_kernel<<<grid, 32, SMEM_BYTES>>>(g_meas, g_state, g_cov, g_F, g_H, g_pn, g_mn,
                                         o_pred, o_state, o_cov, B);
}

// round 10
// speedup vs baseline: 1.1078x; 1.1078x over previous
#include <cuda_runtime.h>

// EKF cell: B=262144, N=8, M=4. Persistent warps, one thread/batch, 32
// batches/tile. Each of 4 independent warps per CTA owns ONE 25.75KB input
// stage + 2 mbarriers, and re-arms the stage MID-TILE (F/P region right after
// unpack, H/pn/mn region after consumption) so the next tile's TMA streams
// while this tile computes -- cross-tile prefetch with single-stage smem.
// Outputs stored directly (scattered STG for cov). 2 CTAs/SM -> 8 warps/SM.
//
// Per-warp stage layout (float4): F[0,512) P[512,1024) H[1024,1280)
// pn[1280,1568) mn[1568,1648). mbars at f4 6592 (16B/warp).

#define STAGE_F4 1648
#define MBAR_BYTE_OFF (4 * STAGE_F4 * 16)     // 105472
#define SMEM_BYTES (MBAR_BYTE_OFF + 64)
#define TXA 16384u     // F + P
#define TXB 9984u      // H + pn + mn

__device__ __forceinline__ float psym(const float* t, int i, int j) {
    return (i >= j) ? t[i*(i+1)/2 + j] : t[j*(j+1)/2 + i];
}
__device__ __forceinline__ unsigned sptr(const void* p) {
    return (unsigned)__cvta_generic_to_shared(p);
}
__device__ __forceinline__ void bulk_g2s(unsigned dst, const void* src,
                                         unsigned bytes, unsigned mbar) {
    asm volatile(
        "cp.async.bulk.shared::cluster.global.mbarrier::complete_tx::bytes [%0], [%1], %2, [%3];"
        :: "r"(dst), "l"(src), "r"(bytes), "r"(mbar) : "memory");
}
__device__ __forceinline__ void mbar_wait(unsigned mbar, int parity) {
    asm volatile(
        "{\n\t"
        ".reg .pred P;\n"
        "W%=:\n\t"
        "mbarrier.try_wait.parity.shared.b64 P, [%0], %1;\n\t"
        "@!P bra W%=;\n\t"
        "}"
        :: "r"(mbar), "r"(parity) : "memory");
}

__global__ __launch_bounds__(128) void ekf_kernel(
    const float* __restrict__ g_meas,
    const float* __restrict__ g_state,
    const float* __restrict__ g_cov,
    const float* __restrict__ g_F,
    const float* __restrict__ g_H,
    const float* __restrict__ g_pn,
    const float* __restrict__ g_mn,
    float* __restrict__ o_pred,
    float* __restrict__ o_state,
    float* __restrict__ o_cov,
    int B)
{
    extern __shared__ __align__(16) float4 smem_all[];

    const int lane = threadIdx.x & 31;
    const int wrp  = threadIdx.x >> 5;
    const int lx   = lane & 7;
    const int tiles = (B + 31) >> 5;
    const int gw = blockIdx.x * 4 + wrp;          // global warp id
    const int GW = gridDim.x * 4;

    float4* sb = smem_all + wrp * STAGE_F4;       // this warp's stage
    const unsigned stg   = sptr(sb);
    const unsigned mbarA = sptr(smem_all) + MBAR_BYTE_OFF + wrp * 16;
    const unsigned mbarB = mbarA + 8;

    // ---------- prologue: init mbars, prefetch first tile ----------
    if (lane == 0) {
        asm volatile("mbarrier.init.shared.b64 [%0], 1;" :: "r"(mbarA) : "memory");
        asm volatile("mbarrier.init.shared.b64 [%0], 1;" :: "r"(mbarB) : "memory");
        asm volatile("fence.proxy.async.shared::cta;" ::: "memory");
        if (gw < tiles) {
            int wb = gw * 32; if (wb + 32 > B) wb = B - 32;
            asm volatile("mbarrier.arrive.expect_tx.shared.b64 _, [%0], %1;"
                         :: "r"(mbarA), "r"(TXA) : "memory");
            bulk_g2s(stg,             g_F   + (size_t)wb * 64, 8192, mbarA);
            bulk_g2s(stg + 512 * 16,  g_cov + (size_t)wb * 64, 8192, mbarA);
            asm volatile("mbarrier.arrive.expect_tx.shared.b64 _, [%0], %1;"
                         :: "r"(mbarB), "r"(TXB) : "memory");
            bulk_g2s(stg + 1024 * 16, g_H   + (size_t)wb * 32, 4096, mbarB);
            bulk_g2s(stg + 1280 * 16, g_pn  + (size_t)wb * 36, 4608, mbarB);
            bulk_g2s(stg + 1568 * 16, g_mn  + (size_t)wb * 10, 1280, mbarB);
        }
    }
    __syncwarp();

    int it = 0;
    for (int tile = gw; tile < tiles; tile += GW, it++) {
        const int par = it & 1;
        int wb = tile * 32; if (wb + 32 > B) wb = B - 32;
        const int b = wb + lane;
        const int ntile = tile + GW;
        int nwb = ntile * 32; if (nwb + 32 > B) nwb = B - 32;
        const bool have_next = (ntile < tiles);

        // per-lane coalesced loads (overlap with TMA wait)
        float st[8]; float4 mv;
        {
            mv = reinterpret_cast<const float4*>(g_meas)[b];
            const float4* s4 = reinterpret_cast<const float4*>(g_state) + (size_t)b * 2;
            float4 a = s4[0], c = s4[1];
            st[0]=a.x; st[1]=a.y; st[2]=a.z; st[3]=a.w;
            st[4]=c.x; st[5]=c.y; st[6]=c.z; st[7]=c.w;
        }

        mbar_wait(mbarA, par);
        __syncwarp();

        // ---- in-place XOR perm of F and P ----
        #pragma unroll
        for (int base = 512; base >= 0; base -= 512) {      // P then F
            float4 t[8];
            #pragma unroll
            for (int k = 0; k < 8; k++) t[k] = sb[base + lane + 32*k];
            __syncwarp();
            #pragma unroll
            for (int k = 0; k < 8; k++) {
                int g = lane + 32*k;
                int bt = g >> 4, sl = g & 15;
                sb[base + bt*16 + (sl ^ (bt & 7))] = t[k];
            }
            __syncwarp();
            #pragma unroll
            for (int k = 0; k < 8; k++) t[k] = sb[base + 256 + lane + 32*k];
            __syncwarp();
            #pragma unroll
            for (int k = 0; k < 8; k++) {
                int g = 256 + lane + 32*k;
                int bt = g >> 4, sl = g & 15;
                sb[base + bt*16 + (sl ^ (bt & 7))] = t[k];
            }
            __syncwarp();
        }

        // ---- unpack F (64) and P (tri 36), conflict-free ----
        float Fm[64];
        #pragma unroll
        for (int v = 0; v < 16; v++) {
            float4 x = sb[lane*16 + ((v & 8) | ((v ^ lx) & 7))];
            Fm[4*v+0] = x.x; Fm[4*v+1] = x.y; Fm[4*v+2] = x.z; Fm[4*v+3] = x.w;
        }
        float Pt[36];
        #pragma unroll
        for (int v = 0; v < 16; v++) {
            float4 x = sb[512 + lane*16 + ((v & 8) | ((v ^ lx) & 7))];
            float vals[4] = {x.x, x.y, x.z, x.w};
            #pragma unroll
            for (int c = 0; c < 4; c++) {
                int e = 4*v + c, i = e >> 3, j = e & 7;
                if (i >= j) Pt[i*(i+1)/2 + j] = vals[c];
            }
        }
        __syncwarp();   // all lanes done with F/P smem

        // ---- re-arm F/P region for next tile (overlaps compute below) ----
        if (have_next && lane == 0) {
            asm volatile("fence.proxy.async.shared::cta;" ::: "memory");
            asm volatile("mbarrier.arrive.expect_tx.shared.b64 _, [%0], %1;"
                         :: "r"(mbarA), "r"(TXA) : "memory");
            bulk_g2s(stg,            g_F   + (size_t)nwb * 64, 8192, mbarA);
            bulk_g2s(stg + 512 * 16, g_cov + (size_t)nwb * 64, 8192, mbarA);
        }

        // ---- new_state = F @ state ----
        float ns[8];
        #pragma unroll
        for (int i = 0; i < 8; i++) {
            float a = 0.f;
            #pragma unroll
            for (int j = 0; j < 8; j++) a += Fm[i*8+j] * st[j];
            ns[i] = a;
        }
        // ---- P' = F P F^T (column-strip, lower tri) ----
        float Pp[36];
        #pragma unroll
        for (int l = 0; l < 8; l++) {
            float g[8];
            #pragma unroll
            for (int j = 0; j < 8; j++) {
                float a = 0.f;
                #pragma unroll
                for (int k = 0; k < 8; k++) a += psym(Pt, j, k) * Fm[l*8+k];
                g[j] = a;
            }
            #pragma unroll
            for (int i = l; i < 8; i++) {
                float a = 0.f;
                #pragma unroll
                for (int j = 0; j < 8; j++) a += Fm[i*8+j] * g[j];
                Pp[i*(i+1)/2 + l] = a;
            }
        }
        // Fm, Pt dead.

        mbar_wait(mbarB, par);
        __syncwarp();

        // ---- in-place XOR perm of H ----
        {
            float4 t[4];
            #pragma unroll
            for (int k = 0; k < 4; k++) t[k] = sb[1024 + lane + 32*k];
            __syncwarp();
            #pragma unroll
            for (int k = 0; k < 4; k++) {
                int g = lane + 32*k;
                int bt = g >> 3, sl = g & 7;
                sb[1024 + bt*8 + (sl ^ (bt & 7))] = t[k];
            }
            __syncwarp();
            #pragma unroll
            for (int k = 0; k < 4; k++) t[k] = sb[1024 + 128 + lane + 32*k];
            __syncwarp();
            #pragma unroll
            for (int k = 0; k < 4; k++) {
                int g = 128 + lane + 32*k;
                int bt = g >> 3, sl = g & 7;
                sb[1024 + bt*8 + (sl ^ (bt & 7))] = t[k];
            }
            __syncwarp();
        }

        // ---- unpack Lq, Hm, Lr; then re-arm H/pn/mn region ----
        float Lq[36];
        #pragma unroll
        for (int v = 0; v < 9; v++) {
            float4 x = sb[1280 + lane*9 + v];
            Lq[4*v+0] = x.x; Lq[4*v+1] = x.y; Lq[4*v+2] = x.z; Lq[4*v+3] = x.w;
        }
        float Hm[32];
        #pragma unroll
        for (int v = 0; v < 8; v++) {
            float4 x = sb[1024 + lane*8 + (v ^ lx)];
            Hm[4*v+0] = x.x; Hm[4*v+1] = x.y; Hm[4*v+2] = x.z; Hm[4*v+3] = x.w;
        }
        float Lr[10];
        {
            const float2* s2 = reinterpret_cast<const float2*>(sb + 1568);
            #pragma unroll
            for (int v = 0; v < 5; v++) {
                float2 x = s2[lane*5 + v];
                Lr[2*v] = x.x; Lr[2*v+1] = x.y;
            }
        }
        __syncwarp();   // all lanes done with H/pn/mn smem

        if (have_next && lane == 0) {
            asm volatile("fence.proxy.async.shared::cta;" ::: "memory");
            asm volatile("mbarrier.arrive.expect_tx.shared.b64 _, [%0], %1;"
                         :: "r"(mbarB), "r"(TXB) : "memory");
            bulk_g2s(stg + 1024 * 16, g_H  + (size_t)nwb * 32, 4096, mbarB);
            bulk_g2s(stg + 1280 * 16, g_pn + (size_t)nwb * 36, 4608, mbarB);
            bulk_g2s(stg + 1568 * 16, g_mn + (size_t)nwb * 10, 1280, mbarB);
        }

        // ---- P' += Q = Lq Lq^T ----
        #pragma unroll
        for (int i = 0; i < 8; i++) {
            #pragma unroll
            for (int l = 0; l <= i; l++) {
                float a = Pp[i*(i+1)/2 + l];
                #pragma unroll
                for (int k = 0; k <= l; k++)
                    a += Lq[i*(i+1)/2 + k] * Lq[l*(l+1)/2 + k];
                Pp[i*(i+1)/2 + l] = a;
            }
        }

        // ---- prediction (stored immediately); residual ----
        float res[4];
        {
            float pr[4];
            #pragma unroll
            for (int i = 0; i < 4; i++) {
                float a = 0.f;
                #pragma unroll
                for (int j = 0; j < 8; j++) a += Hm[i*8+j] * ns[j];
                pr[i] = a;
            }
            reinterpret_cast<float4*>(o_pred)[b] = make_float4(pr[0], pr[1], pr[2], pr[3]);
            res[0] = mv.x - pr[0]; res[1] = mv.y - pr[1];
            res[2] = mv.z - pr[2]; res[3] = mv.w - pr[3];
        }

        // ---- PHt = P' @ H^T ----
        float PHt[32];
        #pragma unroll
        for (int i = 0; i < 8; i++) {
            #pragma unroll
            for (int j = 0; j < 4; j++) {
                float a = 0.f;
                #pragma unroll
                for (int k = 0; k < 8; k++) a += psym(Pp, i, k) * Hm[j*8+k];
                PHt[i*4+j] = a;
            }
        }

        // ---- S = H @ PHt + R ----
        float A[16];
        #pragma unroll
        for (int i = 0; i < 4; i++) {
            #pragma unroll
            for (int j = 0; j < 4; j++) {
                float a = 0.f;
                #pragma unroll
                for (int k = 0; k <= ((i < j) ? i : j); k++)
                    a += Lr[i*(i+1)/2 + k] * Lr[j*(j+1)/2 + k];
                #pragma unroll
                for (int k = 0; k < 8; k++) a += Hm[i*8+k] * PHt[k*4+j];
                A[i*4+j] = a;
            }
        }

        // ---- Gauss-Jordan solve S X = [PHt^T | res] ----
        float Rh[36];
        #pragma unroll
        for (int r = 0; r < 4; r++) {
            #pragma unroll
            for (int c = 0; c < 8; c++) Rh[r*9+c] = PHt[c*4+r];
            Rh[r*9+8] = res[r];
        }
        #pragma unroll
        for (int c = 0; c < 4; c++) {
            float inv = 1.0f / A[c*4+c];
            #pragma unroll
            for (int j = 0; j < 4; j++) A[c*4+j] *= inv;
            #pragma unroll
            for (int j = 0; j < 9; j++) Rh[c*9+j] *= inv;
            #pragma unroll
            for (int r = 0; r < 4; r++) {
                if (r == c) continue;
                float f = A[r*4+c];
                #pragma unroll
                for (int j = 0; j < 4; j++) A[r*4+j] -= f * A[c*4+j];
                #pragma unroll
                for (int j = 0; j < 9; j++) Rh[r*9+j] -= f * Rh[c*9+j];
            }
        }

        // ---- upd_state; store ----
        {
            float us[8];
            #pragma unroll
            for (int i = 0; i < 8; i++) {
                float a = ns[i];
                #pragma unroll
                for (int j = 0; j < 4; j++) a += PHt[i*4+j] * Rh[j*9+8];
                us[i] = a;
            }
            float4* s4o = reinterpret_cast<float4*>(o_state) + (size_t)b * 2;
            s4o[0] = make_float4(us[0], us[1], us[2], us[3]);
            s4o[1] = make_float4(us[4], us[5], us[6], us[7]);
        }

        // ---- upd_cov = P' - PHt X; direct (scattered) STG.128 ----
        float UC[36];
        #pragma unroll
        for (int i = 0; i < 8; i++) {
            #pragma unroll
            for (int l = 0; l <= i; l++) {
                float a = Pp[i*(i+1)/2 + l];
                #pragma unroll
                for (int j = 0; j < 4; j++) a -= PHt[i*4+j] * Rh[j*9+l];
                UC[i*(i+1)/2 + l] = a;
            }
        }
        float4* c4 = reinterpret_cast<float4*>(o_cov) + (size_t)b * 16;
        #pragma unroll
        for (int v = 0; v < 16; v++) {
            int e = 4*v;
            c4[v] = make_float4(
                psym(UC, (e+0) >> 3, (e+0) & 7),
                psym(UC, (e+1) >> 3, (e+1) & 7),
                psym(UC, (e+2) >> 3, (e+2) & 7),
                psym(UC, (e+3) >> 3, (e+3) & 7));
        }
        __syncwarp();
    }
}

extern "C" void kernel_launch(void* const* d_in, const int* in_sizes, int n_in,
                              void* d_out, int out_size)
{
    const float* g_meas = (const float*)d_in[0];
    const float* g_state = (const float*)d_in[1];
    const float* g_cov  = (const float*)d_in[2];
    const float* g_F    = (const float*)d_in[3];
    const float* g_H    = (const float*)d_in[4];
    const float* g_pn   = (const float*)d_in[5];
    const float* g_mn   = (const float*)d_in[6];

    int B = in_sizes[0] / 4;   // measurement is (B, 4)

    float* o_pred  = (float*)d_out;
    float* o_state = o_pred + (size_t)B * 4;
    float* o_cov   = o_state + (size_t)B * 8;

    cudaFuncSetAttribute(ekf_kernel, cudaFuncAttributeMaxDynamicSharedMemorySize,
                         SMEM_BYTES);

    int tiles = (B + 31) / 32;
    int grid = 304;                       // 152 SMs x 2 CTAs (GB300)
    if (grid > tiles) grid = tiles;
    ekf_kernel<<<grid, 128, SMEM_BYTES>>>(g_meas, g_state, g_cov, g_F, g_H, g_pn, g_mn,
                                          o_pred, o_state, o_cov, B);
}